// round 7
// baseline (speedup 1.0000x reference)
#include <cuda_runtime.h>
#include <cstdint>

// Problem constants (match reference)
#define BN 64
#define TN 1024
#define DN 256
#define KMAX 128
#define EPSF 1e-3f
#define MMAXT 64                        // lgamma table depth
#define HALF_L2PI 0.91893853320467274f  // 0.5*log(2*pi)
#define LN2F 0.69314718055994531f
#define LOG2EF 1.44269504088896340f
// C1 = ln(log2e) - 0.5*ln(pi)  (per-nonzero-obs constant from log2 scaling)
#define C1F (-0.20585202294f)

// ---------------------------------------------------------------------------
// Static device scratch
// ---------------------------------------------------------------------------
__device__ int   g_cnt [BN * KMAX];
__device__ int   g_list[BN * KMAX * TN];

// per-dim packed loop constants: {kappa0, a, kl2, cb}
__device__ float4 g_c4[DN];
// fallback-path constants
__device__ float g_a0[DN], g_b0[DN];
__device__ float g_lgA0B0[DN], g_lgA0[DN], g_lgB0[DN], g_lgA[DN], g_lgK[DN];

// lgamma difference tables (telescoped chain-end sums)
__device__ float g_tabNZ[MMAXT * DN];   // [lg(a0+m)-lg(a0)] + [lg(a+m/2)-lg(a)] + [lg(k0+m)-lg(k0)]
__device__ float g_tabB0[MMAXT * DN];   // lg(b0+m)-lg(b0)
__device__ float g_tabAB[MMAXT * DN];   // lg(a0+b0+m)-lg(a0+b0)

// ---------------------------------------------------------------------------
// Fast lgamma for x > 0: shift to x>=8 (unrolled, predicated), then Stirling.
// ---------------------------------------------------------------------------
__device__ __forceinline__ float fast_lgamma(float x)
{
    float prod = 1.0f;
#pragma unroll
    for (int i = 0; i < 8; i++) {
        if (x < 8.0f) { prod *= x; x += 1.0f; }
    }
    float rx  = __frcp_rn(x);
    float rx2 = rx * rx;
    float ser = rx * (8.33333333e-2f + rx2 * (-2.77777778e-3f + rx2 * 7.93650794e-4f));
    float lx  = __logf(x);
    return fmaf(x - 0.5f, lx, -x) + HALF_L2PI + ser - __logf(prod);
}

// ---------------------------------------------------------------------------
// Kernel 1 (fused prep): blocks [0, MMAXT) build lgamma tables + constants;
// blocks [MMAXT, MMAXT+8) build per-(b,k) time lists (one warp per batch row).
// ---------------------------------------------------------------------------
__global__ void __launch_bounds__(256)
k_prep(const float* __restrict__ loc,
       const float* __restrict__ log_mean_conc,
       const float* __restrict__ log_conc,
       const float* __restrict__ log_scale,
       const float* __restrict__ sparse_prior_logit,
       const int*   __restrict__ z,
       float* __restrict__ out)
{
    if (blockIdx.x < MMAXT) {
        const int m = blockIdx.x;
        const int d = threadIdx.x;
        float kappa0 = expf(fminf(log_mean_conc[d], 12.0f));
        float a      = expf(log_conc[d]);
        float b      = expf(log_scale[d]);
        float a0     = 2.0f * a + 4.0f;                 // nu+1, nu = 2a+3
        float b0     = a0 * expf(sparse_prior_logit[d]);
        float l      = loc[d];

        float lgA0 = fast_lgamma(a0);
        float lgB0 = fast_lgamma(b0);
        float lgAB = fast_lgamma(a0 + b0);
        float lgA  = fast_lgamma(a);
        float lgK  = fast_lgamma(kappa0);

        if (m == 0) {
            g_c4[d] = make_float4(kappa0, a,
                                  LOG2EF * kappa0 * l,
                                  (LOG2EF * LOG2EF) * fmaf(kappa0 * l, l, 2.0f * b));
            g_a0[d]     = a0;
            g_b0[d]     = b0;
            // exact bases for the (rare) cnt>=MMAXT fallback path
            g_lgA0[d]   = lgammaf(a0);
            g_lgB0[d]   = lgammaf(b0);
            g_lgA0B0[d] = lgammaf(a0 + b0);
            g_lgA[d]    = lgammaf(a);
            g_lgK[d]    = lgammaf(kappa0);
            if (d < BN) out[d] = 0.0f;                  // out is poisoned
        }

        float fm = (float)m;
        g_tabNZ[m * DN + d] = (fast_lgamma(a0 + fm)           - lgA0)
                            + (fast_lgamma(fmaf(0.5f, fm, a)) - lgA)
                            + (fast_lgamma(kappa0 + fm)       - lgK);
        g_tabB0[m * DN + d] = fast_lgamma(b0 + fm)            - lgB0;
        g_tabAB[m * DN + d] = fast_lgamma(a0 + b0 + fm)       - lgAB;
    } else {
        // ---- list build: one warp per batch row ----
        __shared__ int cs[8][KMAX];
        const int wl   = threadIdx.x >> 5;
        const int lane = threadIdx.x & 31;
        const int b    = (blockIdx.x - MMAXT) * 8 + wl;

        for (int i = threadIdx.x; i < 8 * KMAX; i += blockDim.x)
            ((int*)cs)[i] = 0;
        __syncthreads();

        const int* zr = z + b * TN;
        int* cw = cs[wl];
        const unsigned lmlt = (1u << lane) - 1u;

        for (int t0 = 0; t0 < TN; t0 += 32) {
            int t  = t0 + lane;
            int zv = __ldg(zr + t);                          // coalesced
            unsigned mask = __match_any_sync(0xffffffffu, zv);
            int rank = __popc(mask & lmlt);                  // stable in-chunk rank
            int base = cw[zv];
            __syncwarp();
            g_list[((size_t)(b * KMAX + zv)) * TN + base + rank] = t;
            if (rank == 0)
                cw[zv] = base + __popc(mask);
            __syncwarp();
        }

        for (int k = lane; k < KMAX; k += 32)
            g_cnt[b * KMAX + k] = cw[k];
    }
}

// ---------------------------------------------------------------------------
// Per-observation update, branchless + division-free (log2 domain).
// State: w = kl2 + Sum(nz*y), s2p = cb + Sum(nz*y^2), kn = kappa0 + m1,
//        an = a + m1/2.  With e = y*kn - w, P = (s2p*kn - w^2)(kn+1),
//        Q = P + e^2:  obs term = an*log2(P) - (an+0.5)*log2(Q)
// (the +log2(kn) residue telescopes into tabNZ; scale residue is C1 per obs).
// ---------------------------------------------------------------------------
__device__ __forceinline__ void obs2(float x,
                                     float& w, float& s2p, float& kn, float& an,
                                     float& acc2)
{
    float nzf = (x > EPSF) ? 1.0f : 0.0f;
    float y   = __log2f(fmaxf(x, EPSF));
    float e   = fmaf(y, kn, -w);
    float t1  = fmaf(s2p, kn, -w * w);
    float kn1 = kn + 1.0f;
    float P   = t1 * kn1;
    float Q   = fmaf(e, e, P);
    float LP  = __log2f(P);
    float LQ  = __log2f(Q);
    float th  = fmaf(an, LP - LQ, -0.5f * LQ);
    acc2 = fmaf(nzf, th, acc2);
    float yn = y * nzf;
    w   += yn;
    s2p  = fmaf(yn, y, s2p);
    kn  += nzf;
    an   = fmaf(0.5f, nzf, an);
}

// Chain-end telescoped terms for one dim (natural units; s1 in log2 units).
__device__ __forceinline__ float tail2(int d, int cnt, float m1, float s1,
                                       float a, float kap)
{
    const int M1 = (int)m1;
    const int Z  = cnt - M1;
    float r = fmaf(C1F, m1, -LN2F * s1);   // folded -0.5*ln(pi), scale fix, -Sum y
    if (cnt < MMAXT) {
        r += g_tabNZ[M1 * DN + d]      // nonzero-obs lgamma ratios (3 fused)
           + g_tabB0[Z  * DN + d]      // Sum log(b0+n0)          (zero obs)
           - g_tabAB[cnt * DN + d];    // -Sum log(a0+b0+ck)
    } else {
        float a0 = g_a0[d], b0 = g_b0[d];
        r += (lgammaf(a0 + m1)             - g_lgA0[d])
           + (lgammaf(b0 + (float)Z)       - g_lgB0[d])
           + (lgammaf(fmaf(0.5f, m1, a))   - g_lgA[d])
           + (lgammaf(kap + m1)            - g_lgK[d])
           - (lgammaf(a0 + b0 + (float)cnt) - g_lgA0B0[d]);
    }
    return r;
}

// ---------------------------------------------------------------------------
// Kernel 2: main chain evaluation.
// One CTA per (b,k) chain, 128 threads; thread t owns dims 2t, 2t+1 and the
// CTA streams its cluster's X rows as coalesced float2 (full 1KB row / iter),
// depth-2 software pipeline on the dependent list->X load chain.
// ---------------------------------------------------------------------------
__global__ void __launch_bounds__(128)
k_main(const float* __restrict__ X, float* __restrict__ out)
{
    const int id = blockIdx.x;            // chain id = b*KMAX + k
    const int b  = id >> 7;
    const int k  = id & (KMAX - 1);
    const int t  = threadIdx.x;           // dims 2t, 2t+1

    const int cnt = g_cnt[id];
    float accN = 0.0f;

    if (cnt > 0) {
        const float4 C0 = __ldg(&g_c4[2 * t]);      // {kappa0, a, kl2, cb} dim 2t
        const float4 C1 = __ldg(&g_c4[2 * t + 1]);  // dim 2t+1

        const int* lst = g_list + (size_t)id * TN;
        const float2* Xb = (const float2*)X + ((size_t)b * TN) * (DN / 2) + t;

        float wa = C0.z, s2a = C0.w, kna = C0.x, ana = C0.y;
        float wb = C1.z, s2b = C1.w, knb = C1.x, anb = C1.y;
        float acc2 = 0.f;

        const int cl = cnt - 1;
        int t0 = __ldg(lst);
        int t1 = __ldg(lst + min(1, cl));
        float2 x0 = __ldcs(Xb + (size_t)t0 * (DN / 2));
        float2 x1 = __ldcs(Xb + (size_t)t1 * (DN / 2));

        for (int j = 0; j < cnt; j++) {
            int jn = min(j + 2, cl);                 // branch-free clamp, depth 2
            int tn = __ldg(lst + jn);
            float2 xn = __ldcs(Xb + (size_t)tn * (DN / 2));
            obs2(x0.x, wa, s2a, kna, ana, acc2);
            obs2(x0.y, wb, s2b, knb, anb, acc2);
            x0 = x1;
            x1 = xn;
        }

        const int d0 = 2 * t;
        float m1a = rintf(kna - C0.x), s1a = wa - C0.z;
        float m1b = rintf(knb - C1.x), s1b = wb - C1.z;
        float r = tail2(d0,     cnt, m1a, s1a, C0.y, C0.x)
                + tail2(d0 + 1, cnt, m1b, s1b, C1.y, C1.x);
        accN = fmaf(LN2F, acc2, r);
    }

    // CRP (fully telescoped): Sum_k lgamma(cnt_k) - lgamma(T+1) per batch row
    if (t == 0) {
        if (cnt > 0) accN += fast_lgamma((float)cnt);
        if (k == 0)  accN -= lgammaf((float)(TN + 1));
    }

    // 4-warp reduction
    const int lane = t & 31, wid = t >> 5;
#pragma unroll
    for (int o = 16; o; o >>= 1)
        accN += __shfl_down_sync(0xffffffffu, accN, o);
    __shared__ float wsum[4];
    if (lane == 0) wsum[wid] = accN;
    __syncthreads();
    if (t == 0)
        atomicAdd(&out[b], -(wsum[0] + wsum[1] + wsum[2] + wsum[3]));
}

// ---------------------------------------------------------------------------
// Entry point. Inputs: X, loc, log_mean_conc, log_conc, log_scale,
// sparse_prior_logit, z. Output: float[BN].
// ---------------------------------------------------------------------------
extern "C" void kernel_launch(void* const* d_in, const int* in_sizes, int n_in,
                              void* d_out, int out_size)
{
    const float* X   = (const float*)d_in[0];
    const float* loc = (const float*)d_in[1];
    const float* lmc = (const float*)d_in[2];
    const float* lc  = (const float*)d_in[3];
    const float* ls  = (const float*)d_in[4];
    const float* spl = (const float*)d_in[5];
    const int*   z   = (const int*)d_in[6];
    float* out = (float*)d_out;

    k_prep<<<MMAXT + BN / 8, 256>>>(loc, lmc, lc, ls, spl, z, out);
    k_main<<<BN * KMAX, 128>>>(X, out);
}

// round 8
// speedup vs baseline: 1.0022x; 1.0022x over previous
#include <cuda_runtime.h>
#include <cstdint>

// Problem constants (match reference)
#define BN 64
#define TN 1024
#define DN 256
#define KMAX 128
#define EPSF 1e-3f
#define MMAXT 64                        // lgamma table depth
#define HALF_L2PI 0.91893853320467274f  // 0.5*log(2*pi)
#define LN2F 0.69314718055994531f
#define LOG2EF 1.44269504088896340f
// C1 = ln(log2e) - 0.5*ln(pi)  (per-nonzero-obs constant from log2 scaling)
#define C1F (-0.20585202294f)

// ---------------------------------------------------------------------------
// Static device scratch
// ---------------------------------------------------------------------------
__device__ int   g_cnt [BN * KMAX];
__device__ int   g_list[BN * KMAX * TN];   // PRE-SCALED row offsets: t * (DN/2)

// per-dim packed loop constants: {kappa0, a, kl2, cb}
__device__ float4 g_c4[DN];
// fallback-path constants
__device__ float g_a0[DN], g_b0[DN];
__device__ float g_lgA0B0[DN], g_lgA0[DN], g_lgB0[DN], g_lgA[DN], g_lgK[DN];

// lgamma difference tables (telescoped chain-end sums)
__device__ float g_tabNZ[MMAXT * DN];   // [lg(a0+m)-lg(a0)] + [lg(a+m/2)-lg(a)] + [lg(k0+m)-lg(k0)]
__device__ float g_tabB0[MMAXT * DN];   // lg(b0+m)-lg(b0)
__device__ float g_tabAB[MMAXT * DN];   // lg(a0+b0+m)-lg(a0+b0)

// ---------------------------------------------------------------------------
// Fast lgamma for x > 0: shift to x>=8 (unrolled, predicated), then Stirling.
// ---------------------------------------------------------------------------
__device__ __forceinline__ float fast_lgamma(float x)
{
    float prod = 1.0f;
#pragma unroll
    for (int i = 0; i < 8; i++) {
        if (x < 8.0f) { prod *= x; x += 1.0f; }
    }
    float rx  = __frcp_rn(x);
    float rx2 = rx * rx;
    float ser = rx * (8.33333333e-2f + rx2 * (-2.77777778e-3f + rx2 * 7.93650794e-4f));
    float lx  = __logf(x);
    return fmaf(x - 0.5f, lx, -x) + HALF_L2PI + ser - __logf(prod);
}

// ---------------------------------------------------------------------------
// Kernel 1 (fused prep): blocks [0, MMAXT) build lgamma tables + constants;
// blocks [MMAXT, MMAXT+8) build per-(b,k) time lists (one warp per batch row).
// ---------------------------------------------------------------------------
__global__ void __launch_bounds__(256)
k_prep(const float* __restrict__ loc,
       const float* __restrict__ log_mean_conc,
       const float* __restrict__ log_conc,
       const float* __restrict__ log_scale,
       const float* __restrict__ sparse_prior_logit,
       const int*   __restrict__ z,
       float* __restrict__ out)
{
    if (blockIdx.x < MMAXT) {
        const int m = blockIdx.x;
        const int d = threadIdx.x;
        float kappa0 = expf(fminf(log_mean_conc[d], 12.0f));
        float a      = expf(log_conc[d]);
        float b      = expf(log_scale[d]);
        float a0     = 2.0f * a + 4.0f;                 // nu+1, nu = 2a+3
        float b0     = a0 * expf(sparse_prior_logit[d]);
        float l      = loc[d];

        float lgA0 = fast_lgamma(a0);
        float lgB0 = fast_lgamma(b0);
        float lgAB = fast_lgamma(a0 + b0);
        float lgA  = fast_lgamma(a);
        float lgK  = fast_lgamma(kappa0);

        if (m == 0) {
            g_c4[d] = make_float4(kappa0, a,
                                  LOG2EF * kappa0 * l,
                                  (LOG2EF * LOG2EF) * fmaf(kappa0 * l, l, 2.0f * b));
            g_a0[d]     = a0;
            g_b0[d]     = b0;
            // exact bases for the (rare) cnt>=MMAXT fallback path
            g_lgA0[d]   = lgammaf(a0);
            g_lgB0[d]   = lgammaf(b0);
            g_lgA0B0[d] = lgammaf(a0 + b0);
            g_lgA[d]    = lgammaf(a);
            g_lgK[d]    = lgammaf(kappa0);
            if (d < BN) out[d] = 0.0f;                  // out is poisoned
        }

        float fm = (float)m;
        g_tabNZ[m * DN + d] = (fast_lgamma(a0 + fm)           - lgA0)
                            + (fast_lgamma(fmaf(0.5f, fm, a)) - lgA)
                            + (fast_lgamma(kappa0 + fm)       - lgK);
        g_tabB0[m * DN + d] = fast_lgamma(b0 + fm)            - lgB0;
        g_tabAB[m * DN + d] = fast_lgamma(a0 + b0 + fm)       - lgAB;
    } else {
        // ---- list build: one warp per batch row ----
        __shared__ int cs[8][KMAX];
        const int wl   = threadIdx.x >> 5;
        const int lane = threadIdx.x & 31;
        const int b    = (blockIdx.x - MMAXT) * 8 + wl;

        for (int i = threadIdx.x; i < 8 * KMAX; i += blockDim.x)
            ((int*)cs)[i] = 0;
        __syncthreads();

        const int* zr = z + b * TN;
        int* cw = cs[wl];
        const unsigned lmlt = (1u << lane) - 1u;

        for (int t0 = 0; t0 < TN; t0 += 32) {
            int t  = t0 + lane;
            int zv = __ldg(zr + t);                          // coalesced
            unsigned mask = __match_any_sync(0xffffffffu, zv);
            int rank = __popc(mask & lmlt);                  // stable in-chunk rank
            int base = cw[zv];
            __syncwarp();
            // store PRE-SCALED float2-row offset: t * (DN/2)
            g_list[((size_t)(b * KMAX + zv)) * TN + base + rank] = t * (DN / 2);
            if (rank == 0)
                cw[zv] = base + __popc(mask);
            __syncwarp();
        }

        for (int k = lane; k < KMAX; k += 32)
            g_cnt[b * KMAX + k] = cw[k];
    }
}

// ---------------------------------------------------------------------------
// Per-observation update, branchless + division-free (log2 domain).
// State: w = kl2 + Sum(nz*y), s2p = cb + Sum(nz*y^2), kn = kappa0 + m1,
//        an = a + m1/2.  With e = y*kn - w, P = (s2p*kn - w^2)(kn+1),
//        Q = P + e^2:  obs term = an*log2(P) - (an+0.5)*log2(Q)
// (the +log2(kn) residue telescopes into tabNZ; scale residue is C1 per obs).
// ---------------------------------------------------------------------------
__device__ __forceinline__ void obs2(float x,
                                     float& w, float& s2p, float& kn, float& an,
                                     float& acc2)
{
    float nzf = (x > EPSF) ? 1.0f : 0.0f;
    float y   = __log2f(fmaxf(x, EPSF));
    float e   = fmaf(y, kn, -w);
    float t1  = fmaf(s2p, kn, -w * w);
    float kn1 = kn + 1.0f;
    float P   = t1 * kn1;
    float Q   = fmaf(e, e, P);
    float LP  = __log2f(P);
    float LQ  = __log2f(Q);
    float th  = fmaf(an, LP - LQ, -0.5f * LQ);
    acc2 = fmaf(nzf, th, acc2);
    float yn = y * nzf;
    w   += yn;
    s2p  = fmaf(yn, y, s2p);
    kn  += nzf;
    an   = fmaf(0.5f, nzf, an);
}

// Chain-end telescoped terms for one dim (natural units; s1 in log2 units).
__device__ __forceinline__ float tail2(int d, int cnt, float m1, float s1,
                                       float a, float kap)
{
    const int M1 = (int)m1;
    const int Z  = cnt - M1;
    float r = fmaf(C1F, m1, -LN2F * s1);   // folded -0.5*ln(pi), scale fix, -Sum y
    if (cnt < MMAXT) {
        r += g_tabNZ[M1 * DN + d]      // nonzero-obs lgamma ratios (3 fused)
           + g_tabB0[Z  * DN + d]      // Sum log(b0+n0)          (zero obs)
           - g_tabAB[cnt * DN + d];    // -Sum log(a0+b0+ck)
    } else {
        float a0 = g_a0[d], b0 = g_b0[d];
        r += (lgammaf(a0 + m1)             - g_lgA0[d])
           + (lgammaf(b0 + (float)Z)       - g_lgB0[d])
           + (lgammaf(fmaf(0.5f, m1, a))   - g_lgA[d])
           + (lgammaf(kap + m1)            - g_lgK[d])
           - (lgammaf(a0 + b0 + (float)cnt) - g_lgA0B0[d]);
    }
    return r;
}

// ---------------------------------------------------------------------------
// Kernel 2: main chain evaluation.
// One CTA per (b,k) chain, 128 threads; thread t owns dims 2t, 2t+1 and the
// CTA streams its cluster's X rows as coalesced float2 (full 1KB row / iter),
// depth-2 software pipeline on the dependent list->X load chain.
// X read with default caching (__ldg): X (64MB) fits L2 (126MB) and is fully
// re-read every graph replay, so cross-replay L2 residency is the fast path.
// ---------------------------------------------------------------------------
__global__ void __launch_bounds__(128)
k_main(const float* __restrict__ X, float* __restrict__ out)
{
    const int id = blockIdx.x;            // chain id = b*KMAX + k
    const int b  = id >> 7;
    const int k  = id & (KMAX - 1);
    const int t  = threadIdx.x;           // dims 2t, 2t+1

    const int cnt = g_cnt[id];
    float accN = 0.0f;

    if (cnt > 0) {
        const float4 C0 = __ldg(&g_c4[2 * t]);      // {kappa0, a, kl2, cb} dim 2t
        const float4 C1 = __ldg(&g_c4[2 * t + 1]);  // dim 2t+1

        const int* lst = g_list + (size_t)id * TN;
        const float2* Xb = (const float2*)X + ((size_t)b * TN) * (DN / 2) + t;

        float wa = C0.z, s2a = C0.w, kna = C0.x, ana = C0.y;
        float wb = C1.z, s2b = C1.w, knb = C1.x, anb = C1.y;
        float acc2 = 0.f;

        const int cl = cnt - 1;
        int o0 = __ldg(lst);                     // pre-scaled row offsets
        int o1 = __ldg(lst + min(1, cl));
        float2 x0 = __ldg(Xb + (size_t)o0);
        float2 x1 = __ldg(Xb + (size_t)o1);

        for (int j = 0; j < cnt; j++) {
            int jn = min(j + 2, cl);             // branch-free clamp, depth 2
            int on = __ldg(lst + jn);
            float2 xn = __ldg(Xb + (size_t)on);
            obs2(x0.x, wa, s2a, kna, ana, acc2);
            obs2(x0.y, wb, s2b, knb, anb, acc2);
            x0 = x1;
            x1 = xn;
        }

        const int d0 = 2 * t;
        float m1a = rintf(kna - C0.x), s1a = wa - C0.z;
        float m1b = rintf(knb - C1.x), s1b = wb - C1.z;
        float r = tail2(d0,     cnt, m1a, s1a, C0.y, C0.x)
                + tail2(d0 + 1, cnt, m1b, s1b, C1.y, C1.x);
        accN = fmaf(LN2F, acc2, r);
    }

    // CRP (fully telescoped): Sum_k lgamma(cnt_k) - lgamma(T+1) per batch row
    if (t == 0) {
        if (cnt > 0) accN += fast_lgamma((float)cnt);
        if (k == 0)  accN -= lgammaf((float)(TN + 1));
    }

    // 4-warp reduction
    const int lane = t & 31, wid = t >> 5;
#pragma unroll
    for (int o = 16; o; o >>= 1)
        accN += __shfl_down_sync(0xffffffffu, accN, o);
    __shared__ float wsum[4];
    if (lane == 0) wsum[wid] = accN;
    __syncthreads();
    if (t == 0)
        atomicAdd(&out[b], -(wsum[0] + wsum[1] + wsum[2] + wsum[3]));
}

// ---------------------------------------------------------------------------
// Entry point. Inputs: X, loc, log_mean_conc, log_conc, log_scale,
// sparse_prior_logit, z. Output: float[BN].
// ---------------------------------------------------------------------------
extern "C" void kernel_launch(void* const* d_in, const int* in_sizes, int n_in,
                              void* d_out, int out_size)
{
    const float* X   = (const float*)d_in[0];
    const float* loc = (const float*)d_in[1];
    const float* lmc = (const float*)d_in[2];
    const float* lc  = (const float*)d_in[3];
    const float* ls  = (const float*)d_in[4];
    const float* spl = (const float*)d_in[5];
    const int*   z   = (const int*)d_in[6];
    float* out = (float*)d_out;

    k_prep<<<MMAXT + BN / 8, 256>>>(loc, lmc, lc, ls, spl, z, out);
    k_main<<<BN * KMAX, 128>>>(X, out);
}